// round 14
// baseline (speedup 1.0000x reference)
#include <cuda_runtime.h>
#include <math_constants.h>
#include <cstdint>

// Each 336-float macro-block = 33 softmax rows:
//   seg0: off   0, 9 x 11 | seg1: off  99, 9 x 11
//   seg2: off 198, 9 x  8 | seg3: off 270, 6 x 11

__constant__ int c_row_off[33] = {
      0,  11,  22,  33,  44,  55,  66,  77,  88,
     99, 110, 121, 132, 143, 154, 165, 176, 187,
    198, 206, 214, 222, 230, 238, 246, 254, 262,
    270, 281, 292, 303, 314, 325
};

__constant__ int c_row_len[33] = {
    11, 11, 11, 11, 11, 11, 11, 11, 11,
    11, 11, 11, 11, 11, 11, 11, 11, 11,
     8,  8,  8,  8,  8,  8,  8,  8,  8,
    11, 11, 11, 11, 11, 11
};

#define MB 20                        // macro-blocks per slab
#define SLAB_FLOATS (MB * 336)       // 6720 floats = 26880 B
#define SLAB_F4     (MB * 84)        // 1680 float4
#define NBUF 4
#define THREADS 512
#define LOOKAHEAD 2
#define CTAS_PER_SM 2
#define SMEM_BYTES (NBUF * SLAB_FLOATS * 4 + 128)   // buffers + mbarriers

__device__ __forceinline__ void bulk_load_g2s(uint32_t dst_smem, const void* src_g,
                                              uint32_t bytes, uint32_t mbar) {
    asm volatile(
        "cp.async.bulk.shared::cta.global.mbarrier::complete_tx::bytes [%0], [%1], %2, [%3];"
        :: "r"(dst_smem), "l"(src_g), "r"(bytes), "r"(mbar) : "memory");
}

__device__ __forceinline__ void bulk_store_s2g(void* dst_g, uint32_t src_smem, uint32_t bytes) {
    asm volatile(
        "cp.async.bulk.global.shared::cta.bulk_group [%0], [%1], %2;"
        :: "l"(dst_g), "r"(src_smem), "r"(bytes) : "memory");
}

__device__ __forceinline__ void mbar_init(uint32_t mbar, uint32_t count) {
    asm volatile("mbarrier.init.shared.b64 [%0], %1;" :: "r"(mbar), "r"(count) : "memory");
}

__device__ __forceinline__ void mbar_expect_tx(uint32_t mbar, uint32_t bytes) {
    asm volatile("mbarrier.arrive.expect_tx.shared.b64 _, [%0], %1;"
                 :: "r"(mbar), "r"(bytes) : "memory");
}

__device__ __forceinline__ void mbar_wait(uint32_t mbar, uint32_t parity) {
    uint32_t done;
    asm volatile(
        "{\n\t.reg .pred p;\n\t"
        "mbarrier.try_wait.parity.acquire.cta.shared::cta.b64 p, [%1], %2;\n\t"
        "selp.b32 %0, 1, 0, p;\n\t}"
        : "=r"(done) : "r"(mbar), "r"(parity) : "memory");
    if (!done) {
        asm volatile(
            "{\n\t.reg .pred P1;\n\t"
            "W_%=:\n\t"
            "mbarrier.try_wait.parity.acquire.cta.shared::cta.b64 P1, [%0], %1, 0x989680;\n\t"
            "@P1 bra.uni D_%=;\n\t"
            "bra.uni W_%=;\n\t"
            "D_%=:\n\t}"
            :: "r"(mbar), "r"(parity) : "memory");
    }
}

__global__ __launch_bounds__(THREADS) void seg_softmax_big(
    const float* __restrict__ x, float* __restrict__ out,
    int n_slabs, int total_f4, int n_mblocks)
{
    extern __shared__ float smem_dyn[];
    // layout: NBUF slab buffers, then mbarriers (8B aligned region)
    float* sbuf0 = smem_dyn;
    uint64_t* mbar_s = (uint64_t*)(smem_dyn + NBUF * SLAB_FLOATS);

    const int tid = threadIdx.x;
    const int slab0 = blockIdx.x;
    if (slab0 >= n_slabs) return;

    uint32_t sb[NBUF], mb[NBUF];
#pragma unroll
    for (int b = 0; b < NBUF; ++b) {
        sb[b] = (uint32_t)__cvta_generic_to_shared(sbuf0 + b * SLAB_FLOATS);
        mb[b] = (uint32_t)__cvta_generic_to_shared(&mbar_s[b]);
    }

    if (tid == 0) {
#pragma unroll
        for (int b = 0; b < NBUF; ++b) mbar_init(mb[b], 1);
    }
    __syncthreads();

    // ---- prologue: issue loads for local iterations 0..LOOKAHEAD-1 ----
    if (tid == 0) {
#pragma unroll
        for (int p = 0; p < LOOKAHEAD; ++p) {
            long s = (long)slab0 + (long)p * gridDim.x;
            if (s < n_slabs) {
                int base = (int)s * SLAB_F4;
                uint32_t bytes = (uint32_t)(min(SLAB_F4, total_f4 - base)) * 16u;
                mbar_expect_tx(mb[p], bytes);
                bulk_load_g2s(sb[p], (const char*)x + (size_t)base * 16, bytes, mb[p]);
            }
        }
    }

    int it = 0;
    for (int slab = slab0; slab < n_slabs; slab += gridDim.x, ++it) {
        const int b  = it & (NBUF - 1);
        const uint32_t ph = (uint32_t)(it >> 2) & 1u;

        // ---- wait for this slab's TMA load ----
        mbar_wait(mb[b], ph);

        // ---- ragged softmax out of smem, in place ----
        float* s = sbuf0 + b * SLAB_FLOATS;
        const int base_mb = slab * MB;
        const int nmb     = min(MB, n_mblocks - base_mb);
        const int nrows   = nmb * 33;

        for (int lr = tid; lr < nrows; lr += THREADS) {
            int mbk = lr / 33;
            int rr  = lr - mbk * 33;
            int rowbase = mbk * 336 + c_row_off[rr];
            int len     = c_row_len[rr];

            float v[11];
            float m = -CUDART_INF_F;
#pragma unroll
            for (int i = 0; i < 11; ++i) {
                float val = (i < len) ? s[rowbase + i] : -CUDART_INF_F;
                v[i] = val;
                m = fmaxf(m, val);
            }

            float sum = 0.0f;
#pragma unroll
            for (int i = 0; i < 11; ++i) {
                float e = __expf(v[i] - m);   // padded lanes -> 0
                v[i] = e;
                sum += e;
            }

            float inv = __fdividef(1.0f, sum);
#pragma unroll
            for (int i = 0; i < 11; ++i) {
                if (i < len) s[rowbase + i] = v[i] * inv;
            }
        }
        __syncthreads();   // all STS of this slab done

        if (tid == 0) {
            asm volatile("fence.proxy.async.shared::cta;" ::: "memory");

            // ---- async store of this slab (no wait here) ----
            {
                int base = slab * SLAB_F4;
                uint32_t bytes = (uint32_t)(min(SLAB_F4, total_f4 - base)) * 16u;
                bulk_store_s2g((char*)out + (size_t)base * 16, sb[b], bytes);
                asm volatile("cp.async.bulk.commit_group;" ::: "memory");
            }

            // ---- issue load for iteration it+LOOKAHEAD ----
            // target buffer (it+2)%4 was stored at it-2; <=2 pending store
            // groups guarantees its smem reads have drained.
            {
                long s2 = (long)slab + (long)LOOKAHEAD * gridDim.x;
                if (s2 < n_slabs) {
                    asm volatile("cp.async.bulk.wait_group.read %0;" :: "n"(LOOKAHEAD) : "memory");
                    int nb = (it + LOOKAHEAD) & (NBUF - 1);
                    int base = (int)s2 * SLAB_F4;
                    uint32_t bytes = (uint32_t)(min(SLAB_F4, total_f4 - base)) * 16u;
                    mbar_expect_tx(mb[nb], bytes);
                    bulk_load_g2s(sb[nb], (const char*)x + (size_t)base * 16, bytes, mb[nb]);
                }
            }
        }
        // no trailing barrier: next iteration's mbar_wait provides the sync
    }

    // drain outstanding bulk stores before exit
    if (tid == 0)
        asm volatile("cp.async.bulk.wait_group 0;" ::: "memory");
}

extern "C" void kernel_launch(void* const* d_in, const int* in_sizes, int n_in,
                              void* d_out, int out_size)
{
    const float* x = (const float*)d_in[0];
    float* out = (float*)d_out;

    int n_elems   = in_sizes[0];
    int n_mblocks = n_elems / 336;
    int total_f4  = n_elems / 4;
    int n_slabs   = (n_mblocks + MB - 1) / MB;

    // allow >48KB dynamic smem (non-allocating attribute set; deterministic)
    cudaFuncSetAttribute(seg_softmax_big,
                         cudaFuncAttributeMaxDynamicSharedMemorySize, SMEM_BYTES);

    int grid = 152 * CTAS_PER_SM;       // 2 CTAs/SM (107.6 KB dyn smem each)
    if (grid > n_slabs) grid = n_slabs;

    seg_softmax_big<<<grid, THREADS, SMEM_BYTES>>>(x, out, n_slabs, total_f4, n_mblocks);
}

// round 15
// speedup vs baseline: 1.0190x; 1.0190x over previous
#include <cuda_runtime.h>
#include <math_constants.h>
#include <cstdint>

// Each 336-float macro-block = 33 softmax rows:
//   seg0: off   0, 9 x 11 | seg1: off  99, 9 x 11
//   seg2: off 198, 9 x  8 | seg3: off 270, 6 x 11

__constant__ int c_row_off[33] = {
      0,  11,  22,  33,  44,  55,  66,  77,  88,
     99, 110, 121, 132, 143, 154, 165, 176, 187,
    198, 206, 214, 222, 230, 238, 246, 254, 262,
    270, 281, 292, 303, 314, 325
};

__constant__ int c_row_len[33] = {
    11, 11, 11, 11, 11, 11, 11, 11, 11,
    11, 11, 11, 11, 11, 11, 11, 11, 11,
     8,  8,  8,  8,  8,  8,  8,  8,  8,
    11, 11, 11, 11, 11, 11
};

#define MB 8                         // macro-blocks per slab
#define SLAB_FLOATS (MB * 336)       // 2688 floats
#define SLAB_F4     (MB * 84)        // 672 float4
#define NBUF 4
#define THREADS 256
#define LOOKAHEAD 2

__device__ __forceinline__ void bulk_load_g2s(uint32_t dst_smem, const void* src_g,
                                              uint32_t bytes, uint32_t mbar) {
    asm volatile(
        "cp.async.bulk.shared::cta.global.mbarrier::complete_tx::bytes [%0], [%1], %2, [%3];"
        :: "r"(dst_smem), "l"(src_g), "r"(bytes), "r"(mbar) : "memory");
}

__device__ __forceinline__ void bulk_store_s2g(void* dst_g, uint32_t src_smem, uint32_t bytes) {
    asm volatile(
        "cp.async.bulk.global.shared::cta.bulk_group [%0], [%1], %2;"
        :: "l"(dst_g), "r"(src_smem), "r"(bytes) : "memory");
}

__device__ __forceinline__ void mbar_init(uint32_t mbar, uint32_t count) {
    asm volatile("mbarrier.init.shared.b64 [%0], %1;" :: "r"(mbar), "r"(count) : "memory");
}

__device__ __forceinline__ void mbar_expect_tx(uint32_t mbar, uint32_t bytes) {
    asm volatile("mbarrier.arrive.expect_tx.shared.b64 _, [%0], %1;"
                 :: "r"(mbar), "r"(bytes) : "memory");
}

__device__ __forceinline__ void mbar_wait(uint32_t mbar, uint32_t parity) {
    uint32_t done;
    asm volatile(
        "{\n\t.reg .pred p;\n\t"
        "mbarrier.try_wait.parity.acquire.cta.shared::cta.b64 p, [%1], %2;\n\t"
        "selp.b32 %0, 1, 0, p;\n\t}"
        : "=r"(done) : "r"(mbar), "r"(parity) : "memory");
    if (!done) {
        asm volatile(
            "{\n\t.reg .pred P1;\n\t"
            "W_%=:\n\t"
            "mbarrier.try_wait.parity.acquire.cta.shared::cta.b64 P1, [%0], %1, 0x989680;\n\t"
            "@P1 bra.uni D_%=;\n\t"
            "bra.uni W_%=;\n\t"
            "D_%=:\n\t}"
            :: "r"(mbar), "r"(parity) : "memory");
    }
}

__global__ __launch_bounds__(THREADS) void seg_softmax_tma(
    const float* __restrict__ x, float* __restrict__ out,
    int n_slabs, int total_f4, int n_mblocks)
{
    __shared__ alignas(128) float sbuf[NBUF][SLAB_FLOATS];   // 43008 B
    __shared__ alignas(8) uint64_t mbar_s[NBUF];

    const int tid = threadIdx.x;
    const int slab0 = blockIdx.x;
    if (slab0 >= n_slabs) return;

    uint32_t sb[NBUF], mb[NBUF];
#pragma unroll
    for (int b = 0; b < NBUF; ++b) {
        sb[b] = (uint32_t)__cvta_generic_to_shared(sbuf[b]);
        mb[b] = (uint32_t)__cvta_generic_to_shared(&mbar_s[b]);
    }

    if (tid == 0) {
#pragma unroll
        for (int b = 0; b < NBUF; ++b) mbar_init(mb[b], 1);
    }
    __syncthreads();

    // ---- prologue: issue loads for local iterations 0..LOOKAHEAD-1 ----
    if (tid == 0) {
#pragma unroll
        for (int p = 0; p < LOOKAHEAD; ++p) {
            long s = (long)slab0 + (long)p * gridDim.x;
            if (s < n_slabs) {
                int base = (int)s * SLAB_F4;
                uint32_t bytes = (uint32_t)(min(SLAB_F4, total_f4 - base)) * 16u;
                mbar_expect_tx(mb[p], bytes);
                bulk_load_g2s(sb[p], (const char*)x + (size_t)base * 16, bytes, mb[p]);
            }
        }
    }

    int it = 0;
    for (int slab = slab0; slab < n_slabs; slab += gridDim.x, ++it) {
        const int b  = it & (NBUF - 1);
        const uint32_t ph = (uint32_t)(it >> 2) & 1u;

        // ---- wait for this slab's TMA load ----
        mbar_wait(mb[b], ph);

        // ---- ragged softmax out of smem, in place ----
        float* s = sbuf[b];
        const int base_mb = slab * MB;
        const int nmb     = min(MB, n_mblocks - base_mb);
        const int nrows   = nmb * 33;

        for (int lr = tid; lr < nrows; lr += THREADS) {
            int mbk = lr / 33;
            int rr  = lr - mbk * 33;
            int rowbase = mbk * 336 + c_row_off[rr];
            int len     = c_row_len[rr];

            float v[11];
            float m = -CUDART_INF_F;
#pragma unroll
            for (int i = 0; i < 11; ++i) {
                float val = (i < len) ? s[rowbase + i] : -CUDART_INF_F;
                v[i] = val;
                m = fmaxf(m, val);
            }

            float sum = 0.0f;
#pragma unroll
            for (int i = 0; i < 11; ++i) {
                float e = __expf(v[i] - m);   // padded lanes -> 0
                v[i] = e;
                sum += e;
            }

            float inv = __fdividef(1.0f, sum);
#pragma unroll
            for (int i = 0; i < 11; ++i) {
                if (i < len) s[rowbase + i] = v[i] * inv;
            }
        }
        __syncthreads();   // all STS of this slab done

        if (tid == 0) {
            // order all generic smem writes before subsequent async-proxy ops
            asm volatile("fence.proxy.async.shared::cta;" ::: "memory");

            // ---- async store of this slab (no wait here) ----
            {
                int base = slab * SLAB_F4;
                uint32_t bytes = (uint32_t)(min(SLAB_F4, total_f4 - base)) * 16u;
                bulk_store_s2g((char*)out + (size_t)base * 16, sb[b], bytes);
                asm volatile("cp.async.bulk.commit_group;" ::: "memory");
            }

            // ---- issue load for iteration it+LOOKAHEAD ----
            // target buffer (it+2)%4 was stored at iteration it-2; allow <=2
            // pending store groups so that store has drained its smem reads.
            {
                long s2 = (long)slab + (long)LOOKAHEAD * gridDim.x;
                if (s2 < n_slabs) {
                    asm volatile("cp.async.bulk.wait_group.read %0;" :: "n"(LOOKAHEAD) : "memory");
                    int nb = (it + LOOKAHEAD) & (NBUF - 1);
                    int base = (int)s2 * SLAB_F4;
                    uint32_t bytes = (uint32_t)(min(SLAB_F4, total_f4 - base)) * 16u;
                    mbar_expect_tx(mb[nb], bytes);
                    bulk_load_g2s(sb[nb], (const char*)x + (size_t)base * 16, bytes, mb[nb]);
                }
            }
        }
        // no trailing barrier: next iteration's mbar_wait provides the sync
    }

    // drain outstanding bulk stores before exit
    if (tid == 0)
        asm volatile("cp.async.bulk.wait_group 0;" ::: "memory");
}

extern "C" void kernel_launch(void* const* d_in, const int* in_sizes, int n_in,
                              void* d_out, int out_size)
{
    const float* x = (const float*)d_in[0];
    float* out = (float*)d_out;

    int n_elems   = in_sizes[0];
    int n_mblocks = n_elems / 336;
    int total_f4  = n_elems / 4;
    int n_slabs   = (n_mblocks + MB - 1) / MB;

    int grid = 152 * 5;                 // 5 CTAs/SM (43 KB smem each)
    if (grid > n_slabs) grid = n_slabs;

    seg_softmax_tma<<<grid, THREADS>>>(x, out, n_slabs, total_f4, n_mblocks);
}

// round 16
// speedup vs baseline: 1.0439x; 1.0244x over previous
#include <cuda_runtime.h>
#include <math_constants.h>
#include <cstdint>

// Each 336-float macro-block = 33 softmax rows:
//   seg0: off   0, 9 x 11 | seg1: off  99, 9 x 11
//   seg2: off 198, 9 x  8 | seg3: off 270, 6 x 11

__constant__ int c_row_off[33] = {
      0,  11,  22,  33,  44,  55,  66,  77,  88,
     99, 110, 121, 132, 143, 154, 165, 176, 187,
    198, 206, 214, 222, 230, 238, 246, 254, 262,
    270, 281, 292, 303, 314, 325
};

__constant__ int c_row_len[33] = {
    11, 11, 11, 11, 11, 11, 11, 11, 11,
    11, 11, 11, 11, 11, 11, 11, 11, 11,
     8,  8,  8,  8,  8,  8,  8,  8,  8,
    11, 11, 11, 11, 11, 11
};

#define MB 8                         // macro-blocks per slab
#define SLAB_FLOATS (MB * 336)       // 2688 floats
#define SLAB_F4     (MB * 84)        // 672 float4
#define NBUF 4
#define THREADS 256
#define LOOKAHEAD 2

// streaming data: single-use lines, evict from L2 ASAP
__device__ __forceinline__ void bulk_load_g2s(uint32_t dst_smem, const void* src_g,
                                              uint32_t bytes, uint32_t mbar) {
    asm volatile(
        "{\n\t"
        ".reg .b64 pol;\n\t"
        "createpolicy.fractional.L2::evict_first.b64 pol, 1.0;\n\t"
        "cp.async.bulk.shared::cta.global.mbarrier::complete_tx::bytes.L2::cache_hint"
        " [%0], [%1], %2, [%3], pol;\n\t"
        "}"
        :: "r"(dst_smem), "l"(src_g), "r"(bytes), "r"(mbar) : "memory");
}

__device__ __forceinline__ void bulk_store_s2g(void* dst_g, uint32_t src_smem, uint32_t bytes) {
    asm volatile(
        "{\n\t"
        ".reg .b64 pol;\n\t"
        "createpolicy.fractional.L2::evict_first.b64 pol, 1.0;\n\t"
        "cp.async.bulk.global.shared::cta.bulk_group.L2::cache_hint"
        " [%0], [%1], %2, pol;\n\t"
        "}"
        :: "l"(dst_g), "r"(src_smem), "r"(bytes) : "memory");
}

__device__ __forceinline__ void mbar_init(uint32_t mbar, uint32_t count) {
    asm volatile("mbarrier.init.shared.b64 [%0], %1;" :: "r"(mbar), "r"(count) : "memory");
}

__device__ __forceinline__ void mbar_expect_tx(uint32_t mbar, uint32_t bytes) {
    asm volatile("mbarrier.arrive.expect_tx.shared.b64 _, [%0], %1;"
                 :: "r"(mbar), "r"(bytes) : "memory");
}

__device__ __forceinline__ void mbar_wait(uint32_t mbar, uint32_t parity) {
    uint32_t done;
    asm volatile(
        "{\n\t.reg .pred p;\n\t"
        "mbarrier.try_wait.parity.acquire.cta.shared::cta.b64 p, [%1], %2;\n\t"
        "selp.b32 %0, 1, 0, p;\n\t}"
        : "=r"(done) : "r"(mbar), "r"(parity) : "memory");
    if (!done) {
        asm volatile(
            "{\n\t.reg .pred P1;\n\t"
            "W_%=:\n\t"
            "mbarrier.try_wait.parity.acquire.cta.shared::cta.b64 P1, [%0], %1, 0x989680;\n\t"
            "@P1 bra.uni D_%=;\n\t"
            "bra.uni W_%=;\n\t"
            "D_%=:\n\t}"
            :: "r"(mbar), "r"(parity) : "memory");
    }
}

__global__ __launch_bounds__(THREADS) void seg_softmax_tma(
    const float* __restrict__ x, float* __restrict__ out,
    int n_slabs, int total_f4, int n_mblocks)
{
    __shared__ alignas(128) float sbuf[NBUF][SLAB_FLOATS];   // 43008 B
    __shared__ alignas(8) uint64_t mbar_s[NBUF];

    const int tid = threadIdx.x;
    const int slab0 = blockIdx.x;
    if (slab0 >= n_slabs) return;

    uint32_t sb[NBUF], mb[NBUF];
#pragma unroll
    for (int b = 0; b < NBUF; ++b) {
        sb[b] = (uint32_t)__cvta_generic_to_shared(sbuf[b]);
        mb[b] = (uint32_t)__cvta_generic_to_shared(&mbar_s[b]);
    }

    if (tid == 0) {
#pragma unroll
        for (int b = 0; b < NBUF; ++b) mbar_init(mb[b], 1);
    }
    __syncthreads();

    // ---- prologue: issue loads for local iterations 0..LOOKAHEAD-1 ----
    if (tid == 0) {
#pragma unroll
        for (int p = 0; p < LOOKAHEAD; ++p) {
            long s = (long)slab0 + (long)p * gridDim.x;
            if (s < n_slabs) {
                int base = (int)s * SLAB_F4;
                uint32_t bytes = (uint32_t)(min(SLAB_F4, total_f4 - base)) * 16u;
                mbar_expect_tx(mb[p], bytes);
                bulk_load_g2s(sb[p], (const char*)x + (size_t)base * 16, bytes, mb[p]);
            }
        }
    }

    int it = 0;
    for (int slab = slab0; slab < n_slabs; slab += gridDim.x, ++it) {
        const int b  = it & (NBUF - 1);
        const uint32_t ph = (uint32_t)(it >> 2) & 1u;

        // ---- wait for this slab's TMA load ----
        mbar_wait(mb[b], ph);

        // ---- ragged softmax out of smem, in place ----
        float* s = sbuf[b];
        const int base_mb = slab * MB;
        const int nmb     = min(MB, n_mblocks - base_mb);
        const int nrows   = nmb * 33;

        for (int lr = tid; lr < nrows; lr += THREADS) {
            int mbk = lr / 33;
            int rr  = lr - mbk * 33;
            int rowbase = mbk * 336 + c_row_off[rr];
            int len     = c_row_len[rr];

            float v[11];
            float m = -CUDART_INF_F;
#pragma unroll
            for (int i = 0; i < 11; ++i) {
                float val = (i < len) ? s[rowbase + i] : -CUDART_INF_F;
                v[i] = val;
                m = fmaxf(m, val);
            }

            float sum = 0.0f;
#pragma unroll
            for (int i = 0; i < 11; ++i) {
                float e = __expf(v[i] - m);   // padded lanes -> 0
                v[i] = e;
                sum += e;
            }

            float inv = __fdividef(1.0f, sum);
#pragma unroll
            for (int i = 0; i < 11; ++i) {
                if (i < len) s[rowbase + i] = v[i] * inv;
            }
        }
        __syncthreads();   // all STS of this slab done

        if (tid == 0) {
            // order all generic smem writes before subsequent async-proxy ops
            asm volatile("fence.proxy.async.shared::cta;" ::: "memory");

            // ---- async store of this slab (no wait here) ----
            {
                int base = slab * SLAB_F4;
                uint32_t bytes = (uint32_t)(min(SLAB_F4, total_f4 - base)) * 16u;
                bulk_store_s2g((char*)out + (size_t)base * 16, sb[b], bytes);
                asm volatile("cp.async.bulk.commit_group;" ::: "memory");
            }

            // ---- issue load for iteration it+LOOKAHEAD ----
            // target buffer (it+2)%4 was stored at iteration it-2; allow <=2
            // pending store groups so that store has drained its smem reads.
            {
                long s2 = (long)slab + (long)LOOKAHEAD * gridDim.x;
                if (s2 < n_slabs) {
                    asm volatile("cp.async.bulk.wait_group.read %0;" :: "n"(LOOKAHEAD) : "memory");
                    int nb = (it + LOOKAHEAD) & (NBUF - 1);
                    int base = (int)s2 * SLAB_F4;
                    uint32_t bytes = (uint32_t)(min(SLAB_F4, total_f4 - base)) * 16u;
                    mbar_expect_tx(mb[nb], bytes);
                    bulk_load_g2s(sb[nb], (const char*)x + (size_t)base * 16, bytes, mb[nb]);
                }
            }
        }
        // no trailing barrier: next iteration's mbar_wait provides the sync
    }

    // drain outstanding bulk stores before exit
    if (tid == 0)
        asm volatile("cp.async.bulk.wait_group 0;" ::: "memory");
}

extern "C" void kernel_launch(void* const* d_in, const int* in_sizes, int n_in,
                              void* d_out, int out_size)
{
    const float* x = (const float*)d_in[0];
    float* out = (float*)d_out;

    int n_elems   = in_sizes[0];
    int n_mblocks = n_elems / 336;
    int total_f4  = n_elems / 4;
    int n_slabs   = (n_mblocks + MB - 1) / MB;

    int grid = 152 * 5;                 // 5 CTAs/SM (43 KB smem each)
    if (grid > n_slabs) grid = n_slabs;

    seg_softmax_tma<<<grid, THREADS>>>(x, out, n_slabs, total_f4, n_mblocks);
}